// round 2
// baseline (speedup 1.0000x reference)
#include <cuda_runtime.h>
#include <cuda_bf16.h>

// GCN 2-layer: x[N,8] -> GCNConv(8,64) -> relu -> GCNConv(64,1)
// Restructured:
//   agg[c] = sum_e norm_e * x[r_e]          (8-dim aggregation, NOT 64)
//   h1 = relu(agg @ W1 + b1); z = h1 @ W2   (per-node, tiny GEMM)
//   out[c] = b2 + sum_e norm_e * z[r_e]     (scalar aggregation)
// Self-loops (w=1) handled analytically: deg init to 1, self terms in node pass.
// NOTE: edge_index is int32 on device (JAX x64 disabled), NOT int64.

#define N_NODES 100000
#define IN_F 8
#define HID_F 64

__device__ float g_deg[N_NODES];                       // deg, then dinv in place
__device__ __align__(16) float g_agg[N_NODES * IN_F];  // layer-1 aggregated inputs
__device__ float g_z[N_NODES];                         // per-node layer-2 scalar

__global__ void k_init() {
    int i = blockIdx.x * blockDim.x + threadIdx.x;
    if (i < N_NODES * IN_F) g_agg[i] = 0.0f;
    if (i < N_NODES) g_deg[i] = 1.0f;  // self-loop weight
}

__global__ void k_deg(const int* __restrict__ col,
                      const float* __restrict__ w, int E) {
    int e = blockIdx.x * blockDim.x + threadIdx.x;
    if (e < E) atomicAdd(&g_deg[__ldg(col + e)], __ldg(w + e));
}

__global__ void k_dinv() {
    int i = blockIdx.x * blockDim.x + threadIdx.x;
    if (i < N_NODES) {
        float d = g_deg[i];
        g_deg[i] = (d > 0.0f) ? rsqrtf(d) : 0.0f;
    }
}

__global__ void k_edgeA(const int* __restrict__ row,
                        const int* __restrict__ col,
                        const float* __restrict__ w,
                        const float* __restrict__ x, int E) {
    int e = blockIdx.x * blockDim.x + threadIdx.x;
    if (e >= E) return;
    int r = __ldg(row + e);
    int c = __ldg(col + e);
    float nrm = g_deg[r] * __ldg(w + e) * g_deg[c];
    const float4* xv = (const float4*)x;
    float4 x0 = __ldg(xv + (size_t)r * 2);
    float4 x1 = __ldg(xv + (size_t)r * 2 + 1);
    float* dst = &g_agg[(size_t)c * IN_F];
    asm volatile("red.global.add.v4.f32 [%0], {%1, %2, %3, %4};"
                 :: "l"(dst), "f"(nrm * x0.x), "f"(nrm * x0.y),
                    "f"(nrm * x0.z), "f"(nrm * x0.w) : "memory");
    asm volatile("red.global.add.v4.f32 [%0], {%1, %2, %3, %4};"
                 :: "l"(dst + 4), "f"(nrm * x1.x), "f"(nrm * x1.y),
                    "f"(nrm * x1.z), "f"(nrm * x1.w) : "memory");
}

__global__ void k_node(const float* __restrict__ x,
                       const float* __restrict__ W1,
                       const float* __restrict__ b1,
                       const float* __restrict__ W2,
                       const float* __restrict__ b2,
                       float* __restrict__ out) {
    __shared__ float sW1[IN_F * HID_F];
    __shared__ float sb1[HID_F];
    __shared__ float sW2[HID_F];
    for (int t = threadIdx.x; t < IN_F * HID_F; t += blockDim.x) sW1[t] = W1[t];
    if (threadIdx.x < HID_F) {
        sb1[threadIdx.x] = b1[threadIdx.x];
        sW2[threadIdx.x] = W2[threadIdx.x];
    }
    __syncthreads();
    int i = blockIdx.x * blockDim.x + threadIdx.x;
    if (i >= N_NODES) return;
    float dinv = g_deg[i];
    float selfn = dinv * dinv;  // self-loop norm: dinv * 1 * dinv
    float a[IN_F];
#pragma unroll
    for (int k = 0; k < IN_F; k++)
        a[k] = g_agg[(size_t)i * IN_F + k] + selfn * __ldg(x + (size_t)i * IN_F + k);
    float zacc = 0.0f;
#pragma unroll
    for (int j = 0; j < HID_F; j++) {
        float h = sb1[j];
#pragma unroll
        for (int k = 0; k < IN_F; k++) h = fmaf(a[k], sW1[k * HID_F + j], h);
        h = fmaxf(h, 0.0f);
        zacc = fmaf(h, sW2[j], zacc);
    }
    g_z[i] = zacc;
    out[i] = b2[0] + selfn * zacc;  // seed output with bias + self-loop term
}

__global__ void k_edgeB(const int* __restrict__ row,
                        const int* __restrict__ col,
                        const float* __restrict__ w,
                        float* __restrict__ out, int E) {
    int e = blockIdx.x * blockDim.x + threadIdx.x;
    if (e >= E) return;
    int r = __ldg(row + e);
    int c = __ldg(col + e);
    float nrm = g_deg[r] * __ldg(w + e) * g_deg[c];
    atomicAdd(&out[c], nrm * g_z[r]);
}

extern "C" void kernel_launch(void* const* d_in, const int* in_sizes, int n_in,
                              void* d_out, int out_size) {
    const float* x = (const float*)d_in[0];
    const int* ei = (const int*)d_in[1];   // int32! (JAX x64 disabled)
    const float* w = (const float*)d_in[2];
    const float* W1 = (const float*)d_in[3];
    const float* b1 = (const float*)d_in[4];
    const float* W2 = (const float*)d_in[5];
    const float* b2 = (const float*)d_in[6];
    float* out = (float*)d_out;

    int E = in_sizes[2];
    const int* row = ei;
    const int* col = ei + E;

    const int T = 256;
    int gInit = (N_NODES * IN_F + T - 1) / T;
    int gEdge = (E + T - 1) / T;
    int gNode = (N_NODES + T - 1) / T;

    k_init<<<gInit, T>>>();
    k_deg<<<gEdge, T>>>(col, w, E);
    k_dinv<<<gNode, T>>>();
    k_edgeA<<<gEdge, T>>>(row, col, w, x, E);
    k_node<<<gNode, T>>>(x, W1, b1, W2, b2, out);
    k_edgeB<<<gEdge, T>>>(row, col, w, out, E);
}

// round 3
// speedup vs baseline: 1.3360x; 1.3360x over previous
#include <cuda_runtime.h>
#include <cuda_bf16.h>

// GCN 2-layer, norm-factored form:
//   y[i]   = dinv[i] * x[i]                      (node pass)
//   aggr[c]= sum_e w_e * y[r_e]                  (edge pass A: no deg gathers)
//   a[i]   = dinv[i] * (aggr[i] + y[i])          (self-loop folded)
//   h1=relu(a@W1+b1); zz[i]=dinv[i]*(h1@W2)      (node pass)
//   acc[c] = sum_e w_e * zz[r_e]                 (edge pass B: scalar)
//   out[i] = b2 + dinv[i] * (acc[i] + zz[i])     (final pass)
// edge_index is int32 on device (JAX x64 disabled).

#define N_NODES 100000
#define IN_F 8
#define HID_F 64

__device__ float g_deg[N_NODES];                       // deg -> dinv in place
__device__ __align__(16) float g_y[N_NODES * IN_F];    // dinv*x
__device__ __align__(16) float g_agg[N_NODES * IN_F];  // raw layer-1 aggregation
__device__ float g_zz[N_NODES];                        // dinv*z
__device__ float g_acc[N_NODES];                       // raw layer-2 aggregation

__global__ void k_init() {
    int i = blockIdx.x * blockDim.x + threadIdx.x;
    if (i < N_NODES * IN_F) g_agg[i] = 0.0f;
    if (i < N_NODES) { g_deg[i] = 1.0f; g_acc[i] = 0.0f; }
}

__global__ void k_deg(const int* __restrict__ col,
                      const float* __restrict__ w, int E) {
    int e = blockIdx.x * blockDim.x + threadIdx.x;
    if (e < E) atomicAdd(&g_deg[__ldg(col + e)], __ldg(w + e));
}

// dinv + y = dinv*x
__global__ void k_prep(const float* __restrict__ x) {
    int i = blockIdx.x * blockDim.x + threadIdx.x;
    if (i >= N_NODES) return;
    float d = g_deg[i];
    float dinv = (d > 0.0f) ? rsqrtf(d) : 0.0f;
    g_deg[i] = dinv;
    const float4* xv = (const float4*)x;
    float4 x0 = __ldg(xv + (size_t)i * 2);
    float4 x1 = __ldg(xv + (size_t)i * 2 + 1);
    float4* yv = (float4*)g_y;
    yv[(size_t)i * 2]     = make_float4(dinv * x0.x, dinv * x0.y, dinv * x0.z, dinv * x0.w);
    yv[(size_t)i * 2 + 1] = make_float4(dinv * x1.x, dinv * x1.y, dinv * x1.z, dinv * x1.w);
}

__global__ void k_edgeA(const int* __restrict__ row,
                        const int* __restrict__ col,
                        const float* __restrict__ w, int E) {
    int e = blockIdx.x * blockDim.x + threadIdx.x;
    if (e >= E) return;
    int r = __ldg(row + e);
    int c = __ldg(col + e);
    float we = __ldg(w + e);
    const float4* yv = (const float4*)g_y;
    float4 y0 = __ldg(yv + (size_t)r * 2);
    float4 y1 = __ldg(yv + (size_t)r * 2 + 1);
    float* dst = &g_agg[(size_t)c * IN_F];
    asm volatile("red.global.add.v4.f32 [%0], {%1, %2, %3, %4};"
                 :: "l"(dst), "f"(we * y0.x), "f"(we * y0.y),
                    "f"(we * y0.z), "f"(we * y0.w) : "memory");
    asm volatile("red.global.add.v4.f32 [%0], {%1, %2, %3, %4};"
                 :: "l"(dst + 4), "f"(we * y1.x), "f"(we * y1.y),
                    "f"(we * y1.z), "f"(we * y1.w) : "memory");
}

__global__ void k_node(const float* __restrict__ W1,
                       const float* __restrict__ b1,
                       const float* __restrict__ W2) {
    __shared__ float sW1[IN_F * HID_F];
    __shared__ float sb1[HID_F];
    __shared__ float sW2[HID_F];
    for (int t = threadIdx.x; t < IN_F * HID_F; t += blockDim.x) sW1[t] = W1[t];
    if (threadIdx.x < HID_F) {
        sb1[threadIdx.x] = b1[threadIdx.x];
        sW2[threadIdx.x] = W2[threadIdx.x];
    }
    __syncthreads();
    int i = blockIdx.x * blockDim.x + threadIdx.x;
    if (i >= N_NODES) return;
    float dinv = g_deg[i];
    float a[IN_F];
#pragma unroll
    for (int k = 0; k < IN_F; k++)
        a[k] = dinv * (g_agg[(size_t)i * IN_F + k] + g_y[(size_t)i * IN_F + k]);
    float zacc = 0.0f;
#pragma unroll
    for (int j = 0; j < HID_F; j++) {
        float h = sb1[j];
#pragma unroll
        for (int k = 0; k < IN_F; k++) h = fmaf(a[k], sW1[k * HID_F + j], h);
        h = fmaxf(h, 0.0f);
        zacc = fmaf(h, sW2[j], zacc);
    }
    g_zz[i] = dinv * zacc;
}

__global__ void k_edgeB(const int* __restrict__ row,
                        const int* __restrict__ col,
                        const float* __restrict__ w, int E) {
    int e = blockIdx.x * blockDim.x + threadIdx.x;
    if (e >= E) return;
    int r = __ldg(row + e);
    int c = __ldg(col + e);
    atomicAdd(&g_acc[c], __ldg(w + e) * g_zz[r]);
}

__global__ void k_final(const float* __restrict__ b2, float* __restrict__ out) {
    int i = blockIdx.x * blockDim.x + threadIdx.x;
    if (i < N_NODES)
        out[i] = b2[0] + g_deg[i] * (g_acc[i] + g_zz[i]);
}

extern "C" void kernel_launch(void* const* d_in, const int* in_sizes, int n_in,
                              void* d_out, int out_size) {
    const float* x = (const float*)d_in[0];
    const int* ei = (const int*)d_in[1];   // int32
    const float* w = (const float*)d_in[2];
    const float* W1 = (const float*)d_in[3];
    const float* b1 = (const float*)d_in[4];
    const float* W2 = (const float*)d_in[5];
    const float* b2 = (const float*)d_in[6];
    float* out = (float*)d_out;

    int E = in_sizes[2];
    const int* row = ei;
    const int* col = ei + E;

    const int T = 256;
    int gInit = (N_NODES * IN_F + T - 1) / T;
    int gEdge = (E + T - 1) / T;
    int gNode = (N_NODES + T - 1) / T;

    k_init<<<gInit, T>>>();
    k_deg<<<gEdge, T>>>(col, w, E);
    k_prep<<<gNode, T>>>(x);
    k_edgeA<<<gEdge, T>>>(row, col, w, E);
    k_node<<<gNode, T>>>(W1, b1, W2);
    k_edgeB<<<gEdge, T>>>(row, col, w, E);
    k_final<<<gNode, T>>>(b2, out);
}

// round 4
// speedup vs baseline: 1.3505x; 1.0109x over previous
#include <cuda_runtime.h>
#include <cuda_bf16.h>

// GCN 2-layer, norm-factored:
//   y[i]    = dinv[i]*x[i];  g_agg seeded with y[i] (self-loop)
//   agg[c] += sum_e w_e * y[r_e]              (edgeA: 1x LDG.256 + 2x red.v4)
//   a[i]    = dinv[i]*agg[i]; h1=relu(a@W1+b1); zz=dinv*(h1@W2); g_acc seeded zz
//   acc[c] += sum_e w_e * zz[r_e]             (edgeB: scalar)
//   out[i]  = b2 + dinv[i]*acc[i]
// edge_index is int32 on device (JAX x64 disabled).

#define N_NODES 100000
#define IN_F 8
#define HID_F 64

__device__ float g_deg[N_NODES];                        // deg -> dinv in place
__device__ __align__(32) float g_y[N_NODES * IN_F];     // dinv*x (gather source)
__device__ __align__(32) float g_agg[N_NODES * IN_F];   // layer-1 agg (seeded y)
__device__ float g_zz[N_NODES];                         // dinv*z (gather source)
__device__ float g_acc[N_NODES];                        // layer-2 agg (seeded zz)

__global__ void k_init() {
    int i = blockIdx.x * blockDim.x + threadIdx.x;
    if (i < N_NODES) g_deg[i] = 1.0f;  // self-loop weight
}

__global__ void k_deg(const int* __restrict__ col,
                      const float* __restrict__ w, int E) {
    int t = blockIdx.x * blockDim.x + threadIdx.x;
    int e0 = t * 4;
    if (e0 + 3 < E) {
        int4 c4 = *(const int4*)(col + e0);
        float4 w4 = *(const float4*)(w + e0);
        atomicAdd(&g_deg[c4.x], w4.x);
        atomicAdd(&g_deg[c4.y], w4.y);
        atomicAdd(&g_deg[c4.z], w4.z);
        atomicAdd(&g_deg[c4.w], w4.w);
    } else {
        for (int e = e0; e < E; e++) atomicAdd(&g_deg[__ldg(col + e)], __ldg(w + e));
    }
}

// dinv; y = dinv*x; seed agg with y (self-loop contribution)
__global__ void k_prep(const float* __restrict__ x) {
    int i = blockIdx.x * blockDim.x + threadIdx.x;
    if (i >= N_NODES) return;
    float d = g_deg[i];
    float dinv = (d > 0.0f) ? rsqrtf(d) : 0.0f;
    g_deg[i] = dinv;
    const float4* xv = (const float4*)x;
    float4 x0 = __ldg(xv + (size_t)i * 2);
    float4 x1 = __ldg(xv + (size_t)i * 2 + 1);
    float4 y0 = make_float4(dinv * x0.x, dinv * x0.y, dinv * x0.z, dinv * x0.w);
    float4 y1 = make_float4(dinv * x1.x, dinv * x1.y, dinv * x1.z, dinv * x1.w);
    ((float4*)g_y)[(size_t)i * 2] = y0;
    ((float4*)g_y)[(size_t)i * 2 + 1] = y1;
    ((float4*)g_agg)[(size_t)i * 2] = y0;
    ((float4*)g_agg)[(size_t)i * 2 + 1] = y1;
}

__device__ __forceinline__ void edgeA_one(int r, int c, float we) {
    float a0, a1, a2, a3, a4, a5, a6, a7;
    asm volatile("ld.global.nc.v8.f32 {%0,%1,%2,%3,%4,%5,%6,%7}, [%8];"
                 : "=f"(a0), "=f"(a1), "=f"(a2), "=f"(a3),
                   "=f"(a4), "=f"(a5), "=f"(a6), "=f"(a7)
                 : "l"(g_y + (size_t)r * IN_F));
    float* dst = &g_agg[(size_t)c * IN_F];
    asm volatile("red.global.add.v4.f32 [%0], {%1, %2, %3, %4};"
                 :: "l"(dst), "f"(we * a0), "f"(we * a1),
                    "f"(we * a2), "f"(we * a3) : "memory");
    asm volatile("red.global.add.v4.f32 [%0], {%1, %2, %3, %4};"
                 :: "l"(dst + 4), "f"(we * a4), "f"(we * a5),
                    "f"(we * a6), "f"(we * a7) : "memory");
}

__global__ void k_edgeA(const int* __restrict__ row,
                        const int* __restrict__ col,
                        const float* __restrict__ w, int E) {
    int t = blockIdx.x * blockDim.x + threadIdx.x;
    int e0 = t * 2;
    if (e0 + 1 < E) {
        int2 r2 = *(const int2*)(row + e0);
        int2 c2 = *(const int2*)(col + e0);
        float2 w2 = *(const float2*)(w + e0);
        edgeA_one(r2.x, c2.x, w2.x);
        edgeA_one(r2.y, c2.y, w2.y);
    } else if (e0 < E) {
        edgeA_one(__ldg(row + e0), __ldg(col + e0), __ldg(w + e0));
    }
}

__global__ void k_node(const float* __restrict__ W1,
                       const float* __restrict__ b1,
                       const float* __restrict__ W2) {
    __shared__ float sW1[IN_F * HID_F];
    __shared__ float sb1[HID_F];
    __shared__ float sW2[HID_F];
    for (int t = threadIdx.x; t < IN_F * HID_F; t += blockDim.x) sW1[t] = W1[t];
    if (threadIdx.x < HID_F) {
        sb1[threadIdx.x] = b1[threadIdx.x];
        sW2[threadIdx.x] = W2[threadIdx.x];
    }
    __syncthreads();
    int i = blockIdx.x * blockDim.x + threadIdx.x;
    if (i >= N_NODES) return;
    float dinv = g_deg[i];
    float4 g0 = ((const float4*)g_agg)[(size_t)i * 2];
    float4 g1 = ((const float4*)g_agg)[(size_t)i * 2 + 1];
    float a[IN_F] = {dinv * g0.x, dinv * g0.y, dinv * g0.z, dinv * g0.w,
                     dinv * g1.x, dinv * g1.y, dinv * g1.z, dinv * g1.w};
    float zacc = 0.0f;
#pragma unroll
    for (int j = 0; j < HID_F; j++) {
        float h = sb1[j];
#pragma unroll
        for (int k = 0; k < IN_F; k++) h = fmaf(a[k], sW1[k * HID_F + j], h);
        h = fmaxf(h, 0.0f);
        zacc = fmaf(h, sW2[j], zacc);
    }
    float zz = dinv * zacc;
    g_zz[i] = zz;
    g_acc[i] = zz;  // self-loop seed
}

__global__ void k_edgeB(const int* __restrict__ row,
                        const int* __restrict__ col,
                        const float* __restrict__ w, int E) {
    int t = blockIdx.x * blockDim.x + threadIdx.x;
    int e0 = t * 4;
    if (e0 + 3 < E) {
        int4 r4 = *(const int4*)(row + e0);
        int4 c4 = *(const int4*)(col + e0);
        float4 w4 = *(const float4*)(w + e0);
        float z0 = __ldg(g_zz + r4.x), z1 = __ldg(g_zz + r4.y);
        float z2 = __ldg(g_zz + r4.z), z3 = __ldg(g_zz + r4.w);
        atomicAdd(&g_acc[c4.x], w4.x * z0);
        atomicAdd(&g_acc[c4.y], w4.y * z1);
        atomicAdd(&g_acc[c4.z], w4.z * z2);
        atomicAdd(&g_acc[c4.w], w4.w * z3);
    } else {
        for (int e = e0; e < E; e++) {
            int r = __ldg(row + e), c = __ldg(col + e);
            atomicAdd(&g_acc[c], __ldg(w + e) * __ldg(g_zz + r));
        }
    }
}

__global__ void k_final(const float* __restrict__ b2, float* __restrict__ out) {
    int i = blockIdx.x * blockDim.x + threadIdx.x;
    if (i < N_NODES)
        out[i] = b2[0] + g_deg[i] * g_acc[i];
}

extern "C" void kernel_launch(void* const* d_in, const int* in_sizes, int n_in,
                              void* d_out, int out_size) {
    const float* x = (const float*)d_in[0];
    const int* ei = (const int*)d_in[1];   // int32
    const float* w = (const float*)d_in[2];
    const float* W1 = (const float*)d_in[3];
    const float* b1 = (const float*)d_in[4];
    const float* W2 = (const float*)d_in[5];
    const float* b2 = (const float*)d_in[6];
    float* out = (float*)d_out;

    int E = in_sizes[2];
    const int* row = ei;
    const int* col = ei + E;

    const int T = 256;
    int gNode = (N_NODES + T - 1) / T;
    int gE2 = ((E + 1) / 2 + T - 1) / T;
    int gE4 = ((E + 3) / 4 + T - 1) / T;

    k_init<<<gNode, T>>>();
    k_deg<<<gE4, T>>>(col, w, E);
    k_prep<<<gNode, T>>>(x);
    k_edgeA<<<gE2, T>>>(row, col, w, E);
    k_node<<<gNode, T>>>(W1, b1, W2);
    k_edgeB<<<gE4, T>>>(row, col, w, E);
    k_final<<<gNode, T>>>(b2, out);
}